// round 15
// baseline (speedup 1.0000x reference)
#include <cuda_runtime.h>
#include <cuda_bf16.h>
#include <cuda_fp16.h>
#include <math.h>
#include <stdint.h>

#define BB 2
#define SS 2048
#define DM 1024
#define NH 16
#define DK 64
#define MTOT (BB * SS)  // 4096

// ---------------- device scratch (allocation-free) ----------------
__device__ float g_bias[NH * (2 * SS - 1)];
__device__ __nv_bfloat16 g_xh[MTOT * DM];     // x bf16 hi/lo (for q,k)
__device__ __nv_bfloat16 g_xl[MTOT * DM];
__device__ __half        g_xh16[MTOT * DM];   // x fp16 hi/lo (for v)
__device__ __half        g_xl16[MTOT * DM];
__device__ __nv_bfloat16 g_wth[2 * DM * DM];  // Wq/Wk ^T hi (K-major)
__device__ __nv_bfloat16 g_wtl[2 * DM * DM];  // lo
__device__ __half        g_wv16[DM * DM];     // Wv^T single fp16
__device__ __half        g_wo16[DM * DM];     // Wo^T single fp16
__device__ __half        g_ch[MTOT * DM];     // ctx fp16 hi (exact split)
__device__ __half        g_cl[MTOT * DM];     // ctx fp16 lo
__device__ __half        g_q16[BB * NH * SS * DK];  // Q single fp16
__device__ __half        g_kh[BB * NH * SS * DK];   // K fp16 hi
__device__ __half        g_kl[BB * NH * SS * DK];   // K fp16 lo
__device__ __half        g_v16[BB * NH * SS * DK];  // V single fp16

// ---------------- PTX helpers (arch-agnostic, sm_80-era) ----------------
__device__ __forceinline__ uint32_t smem_u32(const void* p) {
    uint32_t a;
    asm("{ .reg .u64 t; cvta.to.shared.u64 t, %1; cvt.u32.u64 %0, t; }"
        : "=r"(a) : "l"(p));
    return a;
}
__device__ __forceinline__ void cp16(uint32_t dst, const void* src) {
    uint64_t g = __cvta_generic_to_global(src);
    asm volatile("cp.async.cg.shared.global [%0], [%1], 16;" :: "r"(dst), "l"(g));
}
#define CP_COMMIT() asm volatile("cp.async.commit_group;" ::: "memory")
#define CP_WAIT(n)  asm volatile("cp.async.wait_group %0;" :: "n"(n) : "memory")

__device__ __forceinline__ void ldsm_x4(uint32_t* r, uint32_t addr) {
    asm volatile("ldmatrix.sync.aligned.m8n8.x4.shared.b16 {%0,%1,%2,%3}, [%4];"
                 : "=r"(r[0]), "=r"(r[1]), "=r"(r[2]), "=r"(r[3]) : "r"(addr));
}
__device__ __forceinline__ void ldsm_x4_t(uint32_t* r, uint32_t addr) {
    asm volatile("ldmatrix.sync.aligned.m8n8.x4.trans.shared.b16 {%0,%1,%2,%3}, [%4];"
                 : "=r"(r[0]), "=r"(r[1]), "=r"(r[2]), "=r"(r[3]) : "r"(addr));
}
__device__ __forceinline__ void mma16816(float* c, const uint32_t* a, const uint32_t* b) {
    asm volatile(
        "mma.sync.aligned.m16n8k16.row.col.f32.bf16.bf16.f32 "
        "{%0,%1,%2,%3}, {%4,%5,%6,%7}, {%8,%9}, {%0,%1,%2,%3};"
        : "+f"(c[0]), "+f"(c[1]), "+f"(c[2]), "+f"(c[3])
        : "r"(a[0]), "r"(a[1]), "r"(a[2]), "r"(a[3]), "r"(b[0]), "r"(b[1]));
}
__device__ __forceinline__ void mma16816h(float* c, const uint32_t* a, const uint32_t* b) {
    asm volatile(
        "mma.sync.aligned.m16n8k16.row.col.f32.f16.f16.f32 "
        "{%0,%1,%2,%3}, {%4,%5,%6,%7}, {%8,%9}, {%0,%1,%2,%3};"
        : "+f"(c[0]), "+f"(c[1]), "+f"(c[2]), "+f"(c[3])
        : "r"(a[0]), "r"(a[1]), "r"(a[2]), "r"(a[3]), "r"(b[0]), "r"(b[1]));
}

// ---------------------------------------------------------------------------
// Fused prep: blocks [0,4096) split x; [4096,8192) transpose+split W;
// [8192,8208) bias table.
// ---------------------------------------------------------------------------
__global__ void __launch_bounds__(256) prep_kernel(
    const float4* __restrict__ src,
    const float* __restrict__ W0, const float* __restrict__ W1,
    const float* __restrict__ W2, const float* __restrict__ W3,
    const float* __restrict__ rel_bias)
{
    int bid = blockIdx.x;
    int tid = threadIdx.x;
    if (bid < 4096) {
        int i = bid * 256 + tid;
        float4 x = src[i];
        __nv_bfloat162 hA = __floats2bfloat162_rn(x.x, x.y);
        __nv_bfloat162 hB = __floats2bfloat162_rn(x.z, x.w);
        __nv_bfloat162 lA = __floats2bfloat162_rn(x.x - __bfloat162float(hA.x),
                                                  x.y - __bfloat162float(hA.y));
        __nv_bfloat162 lB = __floats2bfloat162_rn(x.z - __bfloat162float(hB.x),
                                                  x.w - __bfloat162float(hB.y));
        *(__nv_bfloat162*)(g_xh + 4 * i) = hA;
        *(__nv_bfloat162*)(g_xh + 4 * i + 2) = hB;
        *(__nv_bfloat162*)(g_xl + 4 * i) = lA;
        *(__nv_bfloat162*)(g_xl + 4 * i + 2) = lB;
        __half2 h16A = __floats2half2_rn(x.x, x.y);
        __half2 h16B = __floats2half2_rn(x.z, x.w);
        __half2 l16A = __floats2half2_rn(x.x - __low2float(h16A),
                                         x.y - __high2float(h16A));
        __half2 l16B = __floats2half2_rn(x.z - __low2float(h16B),
                                         x.w - __high2float(h16B));
        *(__half2*)(g_xh16 + 4 * i) = h16A;
        *(__half2*)(g_xh16 + 4 * i + 2) = h16B;
        *(__half2*)(g_xl16 + 4 * i) = l16A;
        *(__half2*)(g_xl16 + 4 * i + 2) = l16B;
    } else if (bid < 8192) {
        __shared__ float t[32][33];
        int e = bid - 4096;
        int z = e >> 10;
        int rem = e & 1023;
        int bx = rem >> 5, by = rem & 31;
        const float* W = z == 0 ? W0 : z == 1 ? W1 : z == 2 ? W2 : W3;
        int k0 = bx * 32, n0 = by * 32;
        int tx = tid & 31, ty = tid >> 5;
#pragma unroll
        for (int r = 0; r < 32; r += 8)
            t[ty + r][tx] = W[(size_t)(k0 + ty + r) * DM + n0 + tx];
        __syncthreads();
#pragma unroll
        for (int r = 0; r < 32; r += 8) {
            float x = t[tx][ty + r];
            size_t o = (size_t)(n0 + ty + r) * DM + k0 + tx;
            if (z < 2) {
                __nv_bfloat16 h = __float2bfloat16_rn(x);
                g_wth[(size_t)z * DM * DM + o] = h;
                g_wtl[(size_t)z * DM * DM + o] =
                    __float2bfloat16_rn(x - __bfloat162float(h));
            } else if (z == 2) {
                g_wv16[o] = __float2half_rn(x);
            } else {
                g_wo16[o] = __float2half_rn(x);
            }
        }
    } else {
        int h = bid - 8192;
        for (int idx = tid; idx < 2 * SS - 1; idx += 256) {
            int rel = idx - (SS - 1);
            int base = (rel > 0) ? 16 : 0;
            int rp = rel < 0 ? -rel : rel;
            int bucket;
            if (rp < 8) {
                bucket = rp;
            } else {
                float v = logf((float)rp * 0.125f) / logf(16.0f) * 8.0f;
                int bb = 8 + (int)v;
                bucket = bb < 15 ? bb : 15;
            }
            g_bias[h * (2 * SS - 1) + idx] = rel_bias[(base + bucket) * NH + h];
        }
    }
}

// ---------------------------------------------------------------------------
// Fused QKV GEMM (unchanged from round 14).
// ---------------------------------------------------------------------------
#define LDK 40
#define A_PER (128 * LDK * 2)
#define B_PER (128 * LDK * 2)
#define BOFF (2 * A_PER)
#define STAGE (2 * A_PER + 2 * B_PER)
#define GSMEM (2 * STAGE)

__global__ void __launch_bounds__(256, 2) gemm_qkv_kernel() {
    const int mode = blockIdx.z;
    const bool isv = (mode == 2);
    const __nv_bfloat16* Ah = isv ? (const __nv_bfloat16*)g_xh16 : g_xh;
    const __nv_bfloat16* Al = isv ? (const __nv_bfloat16*)g_xl16 : g_xl;
    const __nv_bfloat16* Bh = isv ? (const __nv_bfloat16*)g_wv16
                                  : g_wth + (size_t)mode * DM * DM;
    const __nv_bfloat16* Bl = isv ? nullptr : g_wtl + (size_t)mode * DM * DM;

    extern __shared__ char sm[];
    const uint32_t smb = smem_u32(sm);
    const int tid = threadIdx.x;
    const int wid = tid >> 5, lane = tid & 31;
    const int wm = wid >> 1, wn = wid & 1;
    const int bm = blockIdx.x * 128, bn = blockIdx.y * 128;

    float acc[2][8][4];
#pragma unroll
    for (int i = 0; i < 2; i++)
#pragma unroll
        for (int j = 0; j < 8; j++)
#pragma unroll
            for (int q = 0; q < 4; q++) acc[i][j][q] = 0.0f;

    const uint32_t aRel = (uint32_t)((wm * 32 + (lane & 15)) * LDK + (lane >> 4) * 8) * 2;
    const uint32_t bRel = (uint32_t)BOFF +
        (uint32_t)((wn * 64 + ((lane >> 4) & 1) * 8 + (lane & 7)) * LDK +
                   ((lane >> 3) & 1) * 8) * 2;

    auto load_stage = [&](int c) {
        uint32_t st = smb + (uint32_t)(c & 1) * STAGE;
        int k0 = c * 32;
#pragma unroll
        for (int i = 0; i < 2; i++) {
            int e = tid + 256 * i;
            int row = e >> 2, kq = e & 3;
            uint32_t d = st + (uint32_t)(row * LDK + kq * 8) * 2;
            size_t ga = (size_t)(bm + row) * DM + k0 + kq * 8;
            size_t gb = (size_t)(bn + row) * DM + k0 + kq * 8;
            cp16(d, Ah + ga);
            cp16(d + A_PER, Al + ga);
            cp16(d + BOFF, Bh + gb);
            if (!isv) cp16(d + BOFF + B_PER, Bl + gb);
        }
    };

    load_stage(0);
    CP_COMMIT();

    for (int c = 0; c < 32; ++c) {
        CP_WAIT(0);
        __syncthreads();
        uint32_t st = smb + (uint32_t)(c & 1) * STAGE;
        uint32_t aBase = st + aRel, bBase = st + bRel;
#pragma unroll
        for (int ks = 0; ks < 2; ++ks) {
            uint32_t koff = ks * 32;
            uint32_t aH[2][4], aL[2][4];
#pragma unroll
            for (int mf = 0; mf < 2; ++mf) {
                ldsm_x4(aH[mf], aBase + koff + mf * (16 * LDK * 2));
                ldsm_x4(aL[mf], aBase + koff + mf * (16 * LDK * 2) + A_PER);
            }
            if (!isv) {
#pragma unroll
                for (int p = 0; p < 4; ++p) {
                    uint32_t bH[4], bL[4];
                    uint32_t ba = bBase + koff + p * (16 * LDK * 2);
                    ldsm_x4(bH, ba);
                    ldsm_x4(bL, ba + B_PER);
#pragma unroll
                    for (int mf = 0; mf < 2; ++mf) {
                        mma16816(acc[mf][2 * p], aH[mf], &bH[0]);
                        mma16816(acc[mf][2 * p + 1], aH[mf], &bH[2]);
                    }
#pragma unroll
                    for (int mf = 0; mf < 2; ++mf) {
                        mma16816(acc[mf][2 * p], aH[mf], &bL[0]);
                        mma16816(acc[mf][2 * p + 1], aH[mf], &bL[2]);
                    }
#pragma unroll
                    for (int mf = 0; mf < 2; ++mf) {
                        mma16816(acc[mf][2 * p], aL[mf], &bH[0]);
                        mma16816(acc[mf][2 * p + 1], aL[mf], &bH[2]);
                    }
                }
            } else {
#pragma unroll
                for (int p = 0; p < 4; ++p) {
                    uint32_t bH[4];
                    ldsm_x4(bH, bBase + koff + p * (16 * LDK * 2));
#pragma unroll
                    for (int mf = 0; mf < 2; ++mf) {
                        mma16816h(acc[mf][2 * p], aH[mf], &bH[0]);
                        mma16816h(acc[mf][2 * p + 1], aH[mf], &bH[2]);
                    }
#pragma unroll
                    for (int mf = 0; mf < 2; ++mf) {
                        mma16816h(acc[mf][2 * p], aL[mf], &bH[0]);
                        mma16816h(acc[mf][2 * p + 1], aL[mf], &bH[2]);
                    }
                }
            }
            if (ks == 0 && c + 1 < 32) {
                load_stage(c + 1);
                CP_COMMIT();
            }
        }
    }

    const int g = lane >> 2, t2 = (lane & 3) * 2;
#pragma unroll
    for (int mf = 0; mf < 2; ++mf) {
#pragma unroll
        for (int nf = 0; nf < 8; ++nf) {
            int n = bn + wn * 64 + nf * 8 + t2;
            int m0 = bm + wm * 32 + mf * 16 + g;
            int m1 = m0 + 8;
            int hh = n >> 6, d = n & 63;
            size_t o0 = (((size_t)(m0 >> 11) * NH + hh) * SS + (m0 & (SS - 1))) * DK + d;
            size_t o1 = (((size_t)(m1 >> 11) * NH + hh) * SS + (m1 & (SS - 1))) * DK + d;
            float v0 = acc[mf][nf][0], v1 = acc[mf][nf][1];
            float v2 = acc[mf][nf][2], v3 = acc[mf][nf][3];
            if (mode == 0) {
                *(__half2*)(g_q16 + o0) = __floats2half2_rn(v0, v1);
                *(__half2*)(g_q16 + o1) = __floats2half2_rn(v2, v3);
            } else if (mode == 2) {
                *(__half2*)(g_v16 + o0) = __floats2half2_rn(v0, v1);
                *(__half2*)(g_v16 + o1) = __floats2half2_rn(v2, v3);
            } else {
                __half2 h0 = __floats2half2_rn(v0, v1);
                __half2 l0 = __floats2half2_rn(v0 - __low2float(h0),
                                               v1 - __high2float(h0));
                __half2 h1 = __floats2half2_rn(v2, v3);
                __half2 l1 = __floats2half2_rn(v2 - __low2float(h1),
                                               v3 - __high2float(h1));
                *(__half2*)(g_kh + o0) = h0;
                *(__half2*)(g_kl + o0) = l0;
                *(__half2*)(g_kh + o1) = h1;
                *(__half2*)(g_kl + o1) = l1;
            }
        }
    }
}

// ---------------------------------------------------------------------------
// Output GEMM (unchanged from round 14).
// ---------------------------------------------------------------------------
#define OBOFF (2 * A_PER)
#define OSTAGE (3 * A_PER)
#define OGSMEM (2 * OSTAGE)

__global__ void __launch_bounds__(256, 2) gemm_out_kernel(float* __restrict__ outp) {
    const __half* Ah = g_ch;
    const __half* Al = g_cl;
    const __half* Bh = g_wo16;

    extern __shared__ char sm[];
    const uint32_t smb = smem_u32(sm);
    const int tid = threadIdx.x;
    const int wid = tid >> 5, lane = tid & 31;
    const int wm = wid >> 1, wn = wid & 1;
    const int bm = blockIdx.x * 128, bn = blockIdx.y * 128;

    float acc[2][8][4];
#pragma unroll
    for (int i = 0; i < 2; i++)
#pragma unroll
        for (int j = 0; j < 8; j++)
#pragma unroll
            for (int q = 0; q < 4; q++) acc[i][j][q] = 0.0f;

    const uint32_t aRel = (uint32_t)((wm * 32 + (lane & 15)) * LDK + (lane >> 4) * 8) * 2;
    const uint32_t bRel = (uint32_t)OBOFF +
        (uint32_t)((wn * 64 + ((lane >> 4) & 1) * 8 + (lane & 7)) * LDK +
                   ((lane >> 3) & 1) * 8) * 2;

    auto load_stage = [&](int c) {
        uint32_t st = smb + (uint32_t)(c & 1) * OSTAGE;
        int k0 = c * 32;
#pragma unroll
        for (int i = 0; i < 2; i++) {
            int e = tid + 256 * i;
            int row = e >> 2, kq = e & 3;
            uint32_t d = st + (uint32_t)(row * LDK + kq * 8) * 2;
            size_t ga = (size_t)(bm + row) * DM + k0 + kq * 8;
            size_t gb = (size_t)(bn + row) * DM + k0 + kq * 8;
            cp16(d, Ah + ga);
            cp16(d + A_PER, Al + ga);
            cp16(d + OBOFF, Bh + gb);
        }
    };

    load_stage(0);
    CP_COMMIT();

    for (int c = 0; c < 32; ++c) {
        CP_WAIT(0);
        __syncthreads();
        uint32_t st = smb + (uint32_t)(c & 1) * OSTAGE;
        uint32_t aBase = st + aRel, bBase = st + bRel;
#pragma unroll
        for (int ks = 0; ks < 2; ++ks) {
            uint32_t koff = ks * 32;
            uint32_t aH[2][4], aL[2][4];
#pragma unroll
            for (int mf = 0; mf < 2; ++mf) {
                ldsm_x4(aH[mf], aBase + koff + mf * (16 * LDK * 2));
                ldsm_x4(aL[mf], aBase + koff + mf * (16 * LDK * 2) + A_PER);
            }
#pragma unroll
            for (int p = 0; p < 4; ++p) {
                uint32_t bH[4];
                ldsm_x4(bH, bBase + koff + p * (16 * LDK * 2));
#pragma unroll
                for (int mf = 0; mf < 2; ++mf) {
                    mma16816h(acc[mf][2 * p], aH[mf], &bH[0]);
                    mma16816h(acc[mf][2 * p + 1], aH[mf], &bH[2]);
                }
#pragma unroll
                for (int mf = 0; mf < 2; ++mf) {
                    mma16816h(acc[mf][2 * p], aL[mf], &bH[0]);
                    mma16816h(acc[mf][2 * p + 1], aL[mf], &bH[2]);
                }
            }
            if (ks == 0 && c + 1 < 32) {
                load_stage(c + 1);
                CP_COMMIT();
            }
        }
    }

    const int g = lane >> 2, t2 = (lane & 3) * 2;
#pragma unroll
    for (int mf = 0; mf < 2; ++mf) {
#pragma unroll
        for (int nf = 0; nf < 8; ++nf) {
            int n = bn + wn * 64 + nf * 8 + t2;
            int m0 = bm + wm * 32 + mf * 16 + g;
            int m1 = m0 + 8;
            *(float2*)(outp + (size_t)m0 * DM + n) =
                make_float2(acc[mf][nf][0], acc[mf][nf][1]);
            *(float2*)(outp + (size_t)m1 * DM + n) =
                make_float2(acc[mf][nf][2], acc[mf][nf][3]);
        }
    }
}

// ---------------------------------------------------------------------------
// Flash attention: BQ=128, BK=64, 8 warps, 3-stage KV ring, SOFTWARE-PIPELINED:
// softmax(kt) runs on s computed LAST iteration; QK(kt+1) refills s; PV(kt).
// QK fp16x2 (Q single, K hi/lo), PV fp16x1.
// ---------------------------------------------------------------------------
#define FPB 144
#define Q_BYTES (128 * FPB)
#define KV_BYTES (64 * FPB)
#define STG_OFF Q_BYTES
#define STG_SZ (3 * KV_BYTES)
#define NKSTG 3
#define BIAS_OFF (STG_OFF + NKSTG * STG_SZ)   // 101376
#define FSMEM (BIAS_OFF + NKSTG * 192 * 4)    // 103680

__global__ void __launch_bounds__(256) flash_kernel() {
    extern __shared__ char sm[];
    const uint32_t smb = smem_u32(sm);
    const int tid = threadIdx.x, wid = tid >> 5, lane = tid & 31;
    const int g = lane >> 2, tq = lane & 3;
    const int qt = blockIdx.x, h = blockIdx.y, b = blockIdx.z;
    const int bh = b * NH + h;

    const __half* Qg = g_q16 + ((size_t)bh * SS + qt * 128) * DK;
    const __half* Kh = g_kh + (size_t)bh * SS * DK;
    const __half* Kl = g_kl + (size_t)bh * SS * DK;
    const __half* Vg = g_v16 + (size_t)bh * SS * DK;
    float* bw = (float*)(sm + BIAS_OFF);

    // Q tile (joins cp.async group 0)
#pragma unroll
    for (int i = 0; i < 4; i++) {
        int e = tid + 256 * i;
        int row = e >> 3, qd = e & 7;
        cp16(smb + row * FPB + qd * 16, Qg + row * DK + qd * 8);
    }

    auto load_kv = [&](int c) {
        uint32_t st = smb + STG_OFF + (uint32_t)(c % NKSTG) * STG_SZ;
#pragma unroll
        for (int i = 0; i < 2; i++) {
            int e = tid + 256 * i;
            int row = e >> 3, qd = e & 7;
            uint32_t d = st + row * FPB + qd * 16;
            size_t src = (size_t)(c * 64 + row) * DK + qd * 8;
            cp16(d, Kh + src);
            cp16(d + KV_BYTES, Kl + src);
            cp16(d + 2 * KV_BYTES, Vg + src);
        }
    };
    auto load_bias = [&](int c) {
        if (tid < 191) {
            int base = h * (2 * SS - 1) + c * 64 - qt * 128 + 1920;
            bw[(c % NKSTG) * 192 + tid] = g_bias[base + tid];
        }
    };

    const uint32_t aAddr = smb + (uint32_t)(wid * 16 + (lane & 15)) * FPB + (lane >> 4) * 16;
    const uint32_t bRel = (uint32_t)((((lane >> 4) & 1) * 8 + (lane & 7)) * FPB +
                                     ((lane >> 3) & 1) * 16);
    const uint32_t vRel = (uint32_t)((lane & 15) * FPB + (lane >> 4) * 16);
    const int r0 = wid * 16 + g;

    float s[8][4];
    auto qk_tile = [&](int c) {
        uint32_t stg = smb + STG_OFF + (uint32_t)(c % NKSTG) * STG_SZ;
#pragma unroll
        for (int j = 0; j < 8; j++)
#pragma unroll
            for (int q = 0; q < 4; q++) s[j][q] = 0.0f;
#pragma unroll
        for (int kk = 0; kk < 4; ++kk) {
            uint32_t aH[4], bH[4][4], bL[4][4];
            ldsm_x4(aH, aAddr + kk * 32);
#pragma unroll
            for (int p = 0; p < 4; ++p) {
                uint32_t ba = stg + bRel + p * (16 * FPB) + kk * 32;
                ldsm_x4(bH[p], ba);
                ldsm_x4(bL[p], ba + KV_BYTES);
            }
#pragma unroll
            for (int p = 0; p < 4; ++p) {
                mma16816h(s[2 * p], aH, &bH[p][0]);
                mma16816h(s[2 * p + 1], aH, &bH[p][2]);
            }
#pragma unroll
            for (int p = 0; p < 4; ++p) {
                mma16816h(s[2 * p], aH, &bL[p][0]);
                mma16816h(s[2 * p + 1], aH, &bL[p][2]);
            }
        }
    };

    // prologue
    load_kv(0);
    CP_COMMIT();
    load_bias(0);
    load_kv(1);
    CP_COMMIT();
    load_bias(1);

    float m_[2] = {-INFINITY, -INFINITY};
    float l_[2] = {0.0f, 0.0f};
    float o[8][4];
#pragma unroll
    for (int j = 0; j < 8; j++)
#pragma unroll
        for (int q = 0; q < 4; q++) o[j][q] = 0.0f;

    CP_WAIT(1);          // group 0 (Q + kv0) complete
    __syncthreads();
    qk_tile(0);          // s = scores(tile 0)

    for (int kt = 0; kt < 32; ++kt) {
        CP_WAIT(0);      // group kt+1 (issued last iter / prologue) complete
        __syncthreads(); // all warps done with stage (kt-1)%3 reads
        if (kt + 2 < 32) {
            load_kv(kt + 2);
            CP_COMMIT();
            load_bias(kt + 2);
        }

        // ---- softmax on s (scores of tile kt, computed last iteration) ----
        const float* bwc = bw + (kt % NKSTG) * 192;
        float mx0 = -INFINITY, mx1 = -INFINITY;
#pragma unroll
        for (int j = 0; j < 8; j++) {
            int c = 8 * j + 2 * tq;
            s[j][0] += bwc[c - r0 + 127];
            s[j][1] += bwc[c + 1 - r0 + 127];
            s[j][2] += bwc[c - (r0 + 8) + 127];
            s[j][3] += bwc[c + 1 - (r0 + 8) + 127];
            mx0 = fmaxf(mx0, fmaxf(s[j][0], s[j][1]));
            mx1 = fmaxf(mx1, fmaxf(s[j][2], s[j][3]));
        }
        mx0 = fmaxf(mx0, __shfl_xor_sync(0xffffffffu, mx0, 1));
        mx0 = fmaxf(mx0, __shfl_xor_sync(0xffffffffu, mx0, 2));
        mx1 = fmaxf(mx1, __shfl_xor_sync(0xffffffffu, mx1, 1));
        mx1 = fmaxf(mx1, __shfl_xor_sync(0xffffffffu, mx1, 2));
        float mn0 = fmaxf(m_[0], mx0), mn1 = fmaxf(m_[1], mx1);
        float al0 = __expf(m_[0] - mn0), al1 = __expf(m_[1] - mn1);

        uint32_t pH[8][2];
        float sum0 = 0.0f, sum1 = 0.0f;
#pragma unroll
        for (int j = 0; j < 8; j++) {
            float e0 = __expf(s[j][0] - mn0), e1 = __expf(s[j][1] - mn0);
            float e2 = __expf(s[j][2] - mn1), e3 = __expf(s[j][3] - mn1);
            sum0 += e0 + e1;
            sum1 += e2 + e3;
            __half2 h01 = __floats2half2_rn(e0, e1);
            __half2 h23 = __floats2half2_rn(e2, e3);
            pH[j][0] = *(uint32_t*)&h01;
            pH[j][1] = *(uint32_t*)&h23;
        }
        sum0 += __shfl_xor_sync(0xffffffffu, sum0, 1);
        sum0 += __shfl_xor_sync(0xffffffffu, sum0, 2);
        sum1 += __shfl_xor_sync(0xffffffffu, sum1, 1);
        sum1 += __shfl_xor_sync(0xffffffffu, sum1, 2);
        l_[0] = l_[0] * al0 + sum0;
        l_[1] = l_[1] * al1 + sum1;
        m_[0] = mn0;
        m_[1] = mn1;
#pragma unroll
        for (int j = 0; j < 8; j++) {
            o[j][0] *= al0; o[j][1] *= al0;
            o[j][2] *= al1; o[j][3] *= al1;
        }

        // ---- QK(kt+1): refill s while tensor pipe still has headroom ----
        if (kt + 1 < 32) qk_tile(kt + 1);

        // ---- PV(kt) ----
        uint32_t vstg = smb + STG_OFF + (uint32_t)(kt % NKSTG) * STG_SZ + 2 * KV_BYTES;
#pragma unroll
        for (int kk = 0; kk < 4; ++kk) {
            uint32_t aPh[4] = {pH[2 * kk][0], pH[2 * kk][1],
                               pH[2 * kk + 1][0], pH[2 * kk + 1][1]};
            uint32_t vh[4][4];
#pragma unroll
            for (int p = 0; p < 4; ++p)
                ldsm_x4_t(vh[p], vstg + vRel + kk * (16 * FPB) + p * 32);
#pragma unroll
            for (int p = 0; p < 4; ++p) {
                mma16816h(o[2 * p], aPh, &vh[p][0]);
                mma16816h(o[2 * p + 1], aPh, &vh[p][2]);
            }
        }
    }

    // ---- epilogue: ctx = O / l, exact fp16 hi/lo ----
    float inv0 = 1.0f / l_[0], inv1 = 1.0f / l_[1];
    size_t rbase = (size_t)b * SS + qt * 128 + wid * 16 + g;
#pragma unroll
    for (int j = 0; j < 8; j++) {
        int col = h * DK + 8 * j + 2 * tq;
        float x0 = o[j][0] * inv0, x1 = o[j][1] * inv0;
        float x2 = o[j][2] * inv1, x3 = o[j][3] * inv1;
        __half2 h0 = __floats2half2_rn(x0, x1);
        __half2 l0 = __floats2half2_rn(x0 - __low2float(h0), x1 - __high2float(h0));
        __half2 h1 = __floats2half2_rn(x2, x3);
        __half2 l1 = __floats2half2_rn(x2 - __low2float(h1), x3 - __high2float(h1));
        *(__half2*)(g_ch + rbase * DM + col) = h0;
        *(__half2*)(g_cl + rbase * DM + col) = l0;
        *(__half2*)(g_ch + (rbase + 8) * DM + col) = h1;
        *(__half2*)(g_cl + (rbase + 8) * DM + col) = l1;
    }
}

// ---------------------------------------------------------------------------
extern "C" void kernel_launch(void* const* d_in, const int* in_sizes, int n_in,
                              void* d_out, int out_size) {
    const float* hs = (const float*)d_in[0];
    const float* Wq = (const float*)d_in[1];
    const float* Wk = (const float*)d_in[2];
    const float* Wv = (const float*)d_in[3];
    const float* Wo = (const float*)d_in[4];
    const float* rb = (const float*)d_in[5];

    cudaFuncSetAttribute(flash_kernel,
                         cudaFuncAttributeMaxDynamicSharedMemorySize, FSMEM);
    cudaFuncSetAttribute(gemm_qkv_kernel,
                         cudaFuncAttributeMaxDynamicSharedMemorySize, GSMEM);
    cudaFuncSetAttribute(gemm_out_kernel,
                         cudaFuncAttributeMaxDynamicSharedMemorySize, OGSMEM);

    prep_kernel<<<8208, 256>>>((const float4*)hs, Wq, Wk, Wv, Wo, rb);
    gemm_qkv_kernel<<<dim3(MTOT / 128, DM / 128, 3), 256, GSMEM>>>();
    flash_kernel<<<dim3(SS / 128, NH, BB), 256, FSMEM>>>();
    gemm_out_kernel<<<dim3(MTOT / 128, DM / 128), 256, OGSMEM>>>((float*)d_out);
}

// round 16
// speedup vs baseline: 1.0481x; 1.0481x over previous
#include <cuda_runtime.h>
#include <cuda_bf16.h>
#include <cuda_fp16.h>
#include <math.h>
#include <stdint.h>

#define BB 2
#define SS 2048
#define DM 1024
#define NH 16
#define DK 64
#define MTOT (BB * SS)  // 4096

// ---------------- device scratch (allocation-free) ----------------
__device__ float g_bias[NH * (2 * SS - 1)];
__device__ __nv_bfloat16 g_xh[MTOT * DM];     // x bf16 hi/lo (for q,k)
__device__ __nv_bfloat16 g_xl[MTOT * DM];
__device__ __half        g_xh16[MTOT * DM];   // x fp16 hi/lo (for v)
__device__ __half        g_xl16[MTOT * DM];
__device__ __nv_bfloat16 g_wth[2 * DM * DM];  // Wq/Wk ^T hi (K-major)
__device__ __nv_bfloat16 g_wtl[2 * DM * DM];  // lo
__device__ __half        g_wv16[DM * DM];     // Wv^T single fp16
__device__ __half        g_wo16[DM * DM];     // Wo^T single fp16
__device__ __half        g_ch[MTOT * DM];     // ctx fp16 hi (exact split)
__device__ __half        g_cl[MTOT * DM];     // ctx fp16 lo
__device__ __half        g_q16[BB * NH * SS * DK];  // Q single fp16
__device__ __half        g_kh[BB * NH * SS * DK];   // K fp16 hi
__device__ __half        g_kl[BB * NH * SS * DK];   // K fp16 lo
__device__ __half        g_v16[BB * NH * SS * DK];  // V single fp16

// ---------------- PTX helpers (arch-agnostic, sm_80-era) ----------------
__device__ __forceinline__ uint32_t smem_u32(const void* p) {
    uint32_t a;
    asm("{ .reg .u64 t; cvta.to.shared.u64 t, %1; cvt.u32.u64 %0, t; }"
        : "=r"(a) : "l"(p));
    return a;
}
__device__ __forceinline__ void cp16(uint32_t dst, const void* src) {
    uint64_t g = __cvta_generic_to_global(src);
    asm volatile("cp.async.cg.shared.global [%0], [%1], 16;" :: "r"(dst), "l"(g));
}
#define CP_COMMIT() asm volatile("cp.async.commit_group;" ::: "memory")
#define CP_WAIT(n)  asm volatile("cp.async.wait_group %0;" :: "n"(n) : "memory")

__device__ __forceinline__ void ldsm_x4(uint32_t* r, uint32_t addr) {
    asm volatile("ldmatrix.sync.aligned.m8n8.x4.shared.b16 {%0,%1,%2,%3}, [%4];"
                 : "=r"(r[0]), "=r"(r[1]), "=r"(r[2]), "=r"(r[3]) : "r"(addr));
}
__device__ __forceinline__ void ldsm_x4_t(uint32_t* r, uint32_t addr) {
    asm volatile("ldmatrix.sync.aligned.m8n8.x4.trans.shared.b16 {%0,%1,%2,%3}, [%4];"
                 : "=r"(r[0]), "=r"(r[1]), "=r"(r[2]), "=r"(r[3]) : "r"(addr));
}
__device__ __forceinline__ void mma16816(float* c, const uint32_t* a, const uint32_t* b) {
    asm volatile(
        "mma.sync.aligned.m16n8k16.row.col.f32.bf16.bf16.f32 "
        "{%0,%1,%2,%3}, {%4,%5,%6,%7}, {%8,%9}, {%0,%1,%2,%3};"
        : "+f"(c[0]), "+f"(c[1]), "+f"(c[2]), "+f"(c[3])
        : "r"(a[0]), "r"(a[1]), "r"(a[2]), "r"(a[3]), "r"(b[0]), "r"(b[1]));
}
__device__ __forceinline__ void mma16816h(float* c, const uint32_t* a, const uint32_t* b) {
    asm volatile(
        "mma.sync.aligned.m16n8k16.row.col.f32.f16.f16.f32 "
        "{%0,%1,%2,%3}, {%4,%5,%6,%7}, {%8,%9}, {%0,%1,%2,%3};"
        : "+f"(c[0]), "+f"(c[1]), "+f"(c[2]), "+f"(c[3])
        : "r"(a[0]), "r"(a[1]), "r"(a[2]), "r"(a[3]), "r"(b[0]), "r"(b[1]));
}

// ---------------------------------------------------------------------------
// Fused prep: blocks [0,4096) split x; [4096,8192) transpose+split W;
// [8192,8208) bias table.
// ---------------------------------------------------------------------------
__global__ void __launch_bounds__(256) prep_kernel(
    const float4* __restrict__ src,
    const float* __restrict__ W0, const float* __restrict__ W1,
    const float* __restrict__ W2, const float* __restrict__ W3,
    const float* __restrict__ rel_bias)
{
    int bid = blockIdx.x;
    int tid = threadIdx.x;
    if (bid < 4096) {
        int i = bid * 256 + tid;
        float4 x = src[i];
        __nv_bfloat162 hA = __floats2bfloat162_rn(x.x, x.y);
        __nv_bfloat162 hB = __floats2bfloat162_rn(x.z, x.w);
        __nv_bfloat162 lA = __floats2bfloat162_rn(x.x - __bfloat162float(hA.x),
                                                  x.y - __bfloat162float(hA.y));
        __nv_bfloat162 lB = __floats2bfloat162_rn(x.z - __bfloat162float(hB.x),
                                                  x.w - __bfloat162float(hB.y));
        *(__nv_bfloat162*)(g_xh + 4 * i) = hA;
        *(__nv_bfloat162*)(g_xh + 4 * i + 2) = hB;
        *(__nv_bfloat162*)(g_xl + 4 * i) = lA;
        *(__nv_bfloat162*)(g_xl + 4 * i + 2) = lB;
        __half2 h16A = __floats2half2_rn(x.x, x.y);
        __half2 h16B = __floats2half2_rn(x.z, x.w);
        __half2 l16A = __floats2half2_rn(x.x - __low2float(h16A),
                                         x.y - __high2float(h16A));
        __half2 l16B = __floats2half2_rn(x.z - __low2float(h16B),
                                         x.w - __high2float(h16B));
        *(__half2*)(g_xh16 + 4 * i) = h16A;
        *(__half2*)(g_xh16 + 4 * i + 2) = h16B;
        *(__half2*)(g_xl16 + 4 * i) = l16A;
        *(__half2*)(g_xl16 + 4 * i + 2) = l16B;
    } else if (bid < 8192) {
        __shared__ float t[32][33];
        int e = bid - 4096;
        int z = e >> 10;
        int rem = e & 1023;
        int bx = rem >> 5, by = rem & 31;
        const float* W = z == 0 ? W0 : z == 1 ? W1 : z == 2 ? W2 : W3;
        int k0 = bx * 32, n0 = by * 32;
        int tx = tid & 31, ty = tid >> 5;
#pragma unroll
        for (int r = 0; r < 32; r += 8)
            t[ty + r][tx] = W[(size_t)(k0 + ty + r) * DM + n0 + tx];
        __syncthreads();
#pragma unroll
        for (int r = 0; r < 32; r += 8) {
            float x = t[tx][ty + r];
            size_t o = (size_t)(n0 + ty + r) * DM + k0 + tx;
            if (z < 2) {
                __nv_bfloat16 h = __float2bfloat16_rn(x);
                g_wth[(size_t)z * DM * DM + o] = h;
                g_wtl[(size_t)z * DM * DM + o] =
                    __float2bfloat16_rn(x - __bfloat162float(h));
            } else if (z == 2) {
                g_wv16[o] = __float2half_rn(x);
            } else {
                g_wo16[o] = __float2half_rn(x);
            }
        }
    } else {
        int h = bid - 8192;
        for (int idx = tid; idx < 2 * SS - 1; idx += 256) {
            int rel = idx - (SS - 1);
            int base = (rel > 0) ? 16 : 0;
            int rp = rel < 0 ? -rel : rel;
            int bucket;
            if (rp < 8) {
                bucket = rp;
            } else {
                float v = logf((float)rp * 0.125f) / logf(16.0f) * 8.0f;
                int bb = 8 + (int)v;
                bucket = bb < 15 ? bb : 15;
            }
            g_bias[h * (2 * SS - 1) + idx] = rel_bias[(base + bucket) * NH + h];
        }
    }
}

// ---------------------------------------------------------------------------
// Fused QKV GEMM (unchanged).
// ---------------------------------------------------------------------------
#define LDK 40
#define A_PER (128 * LDK * 2)
#define B_PER (128 * LDK * 2)
#define BOFF (2 * A_PER)
#define STAGE (2 * A_PER + 2 * B_PER)
#define GSMEM (2 * STAGE)

__global__ void __launch_bounds__(256, 2) gemm_qkv_kernel() {
    const int mode = blockIdx.z;
    const bool isv = (mode == 2);
    const __nv_bfloat16* Ah = isv ? (const __nv_bfloat16*)g_xh16 : g_xh;
    const __nv_bfloat16* Al = isv ? (const __nv_bfloat16*)g_xl16 : g_xl;
    const __nv_bfloat16* Bh = isv ? (const __nv_bfloat16*)g_wv16
                                  : g_wth + (size_t)mode * DM * DM;
    const __nv_bfloat16* Bl = isv ? nullptr : g_wtl + (size_t)mode * DM * DM;

    extern __shared__ char sm[];
    const uint32_t smb = smem_u32(sm);
    const int tid = threadIdx.x;
    const int wid = tid >> 5, lane = tid & 31;
    const int wm = wid >> 1, wn = wid & 1;
    const int bm = blockIdx.x * 128, bn = blockIdx.y * 128;

    float acc[2][8][4];
#pragma unroll
    for (int i = 0; i < 2; i++)
#pragma unroll
        for (int j = 0; j < 8; j++)
#pragma unroll
            for (int q = 0; q < 4; q++) acc[i][j][q] = 0.0f;

    const uint32_t aRel = (uint32_t)((wm * 32 + (lane & 15)) * LDK + (lane >> 4) * 8) * 2;
    const uint32_t bRel = (uint32_t)BOFF +
        (uint32_t)((wn * 64 + ((lane >> 4) & 1) * 8 + (lane & 7)) * LDK +
                   ((lane >> 3) & 1) * 8) * 2;

    auto load_stage = [&](int c) {
        uint32_t st = smb + (uint32_t)(c & 1) * STAGE;
        int k0 = c * 32;
#pragma unroll
        for (int i = 0; i < 2; i++) {
            int e = tid + 256 * i;
            int row = e >> 2, kq = e & 3;
            uint32_t d = st + (uint32_t)(row * LDK + kq * 8) * 2;
            size_t ga = (size_t)(bm + row) * DM + k0 + kq * 8;
            size_t gb = (size_t)(bn + row) * DM + k0 + kq * 8;
            cp16(d, Ah + ga);
            cp16(d + A_PER, Al + ga);
            cp16(d + BOFF, Bh + gb);
            if (!isv) cp16(d + BOFF + B_PER, Bl + gb);
        }
    };

    load_stage(0);
    CP_COMMIT();

    for (int c = 0; c < 32; ++c) {
        CP_WAIT(0);
        __syncthreads();
        uint32_t st = smb + (uint32_t)(c & 1) * STAGE;
        uint32_t aBase = st + aRel, bBase = st + bRel;
#pragma unroll
        for (int ks = 0; ks < 2; ++ks) {
            uint32_t koff = ks * 32;
            uint32_t aH[2][4], aL[2][4];
#pragma unroll
            for (int mf = 0; mf < 2; ++mf) {
                ldsm_x4(aH[mf], aBase + koff + mf * (16 * LDK * 2));
                ldsm_x4(aL[mf], aBase + koff + mf * (16 * LDK * 2) + A_PER);
            }
            if (!isv) {
#pragma unroll
                for (int p = 0; p < 4; ++p) {
                    uint32_t bH[4], bL[4];
                    uint32_t ba = bBase + koff + p * (16 * LDK * 2);
                    ldsm_x4(bH, ba);
                    ldsm_x4(bL, ba + B_PER);
#pragma unroll
                    for (int mf = 0; mf < 2; ++mf) {
                        mma16816(acc[mf][2 * p], aH[mf], &bH[0]);
                        mma16816(acc[mf][2 * p + 1], aH[mf], &bH[2]);
                    }
#pragma unroll
                    for (int mf = 0; mf < 2; ++mf) {
                        mma16816(acc[mf][2 * p], aH[mf], &bL[0]);
                        mma16816(acc[mf][2 * p + 1], aH[mf], &bL[2]);
                    }
#pragma unroll
                    for (int mf = 0; mf < 2; ++mf) {
                        mma16816(acc[mf][2 * p], aL[mf], &bH[0]);
                        mma16816(acc[mf][2 * p + 1], aL[mf], &bH[2]);
                    }
                }
            } else {
#pragma unroll
                for (int p = 0; p < 4; ++p) {
                    uint32_t bH[4];
                    ldsm_x4(bH, bBase + koff + p * (16 * LDK * 2));
#pragma unroll
                    for (int mf = 0; mf < 2; ++mf) {
                        mma16816h(acc[mf][2 * p], aH[mf], &bH[0]);
                        mma16816h(acc[mf][2 * p + 1], aH[mf], &bH[2]);
                    }
#pragma unroll
                    for (int mf = 0; mf < 2; ++mf) {
                        mma16816h(acc[mf][2 * p], aL[mf], &bH[0]);
                        mma16816h(acc[mf][2 * p + 1], aL[mf], &bH[2]);
                    }
                }
            }
            if (ks == 0 && c + 1 < 32) {
                load_stage(c + 1);
                CP_COMMIT();
            }
        }
    }

    const int g = lane >> 2, t2 = (lane & 3) * 2;
#pragma unroll
    for (int mf = 0; mf < 2; ++mf) {
#pragma unroll
        for (int nf = 0; nf < 8; ++nf) {
            int n = bn + wn * 64 + nf * 8 + t2;
            int m0 = bm + wm * 32 + mf * 16 + g;
            int m1 = m0 + 8;
            int hh = n >> 6, d = n & 63;
            size_t o0 = (((size_t)(m0 >> 11) * NH + hh) * SS + (m0 & (SS - 1))) * DK + d;
            size_t o1 = (((size_t)(m1 >> 11) * NH + hh) * SS + (m1 & (SS - 1))) * DK + d;
            float v0 = acc[mf][nf][0], v1 = acc[mf][nf][1];
            float v2 = acc[mf][nf][2], v3 = acc[mf][nf][3];
            if (mode == 0) {
                *(__half2*)(g_q16 + o0) = __floats2half2_rn(v0, v1);
                *(__half2*)(g_q16 + o1) = __floats2half2_rn(v2, v3);
            } else if (mode == 2) {
                *(__half2*)(g_v16 + o0) = __floats2half2_rn(v0, v1);
                *(__half2*)(g_v16 + o1) = __floats2half2_rn(v2, v3);
            } else {
                __half2 h0 = __floats2half2_rn(v0, v1);
                __half2 l0 = __floats2half2_rn(v0 - __low2float(h0),
                                               v1 - __high2float(h0));
                __half2 h1 = __floats2half2_rn(v2, v3);
                __half2 l1 = __floats2half2_rn(v2 - __low2float(h1),
                                               v3 - __high2float(h1));
                *(__half2*)(g_kh + o0) = h0;
                *(__half2*)(g_kl + o0) = l0;
                *(__half2*)(g_kh + o1) = h1;
                *(__half2*)(g_kl + o1) = l1;
            }
        }
    }
}

// ---------------------------------------------------------------------------
// Output GEMM (unchanged).
// ---------------------------------------------------------------------------
#define OBOFF (2 * A_PER)
#define OSTAGE (3 * A_PER)
#define OGSMEM (2 * OSTAGE)

__global__ void __launch_bounds__(256, 2) gemm_out_kernel(float* __restrict__ outp) {
    const __half* Ah = g_ch;
    const __half* Al = g_cl;
    const __half* Bh = g_wo16;

    extern __shared__ char sm[];
    const uint32_t smb = smem_u32(sm);
    const int tid = threadIdx.x;
    const int wid = tid >> 5, lane = tid & 31;
    const int wm = wid >> 1, wn = wid & 1;
    const int bm = blockIdx.x * 128, bn = blockIdx.y * 128;

    float acc[2][8][4];
#pragma unroll
    for (int i = 0; i < 2; i++)
#pragma unroll
        for (int j = 0; j < 8; j++)
#pragma unroll
            for (int q = 0; q < 4; q++) acc[i][j][q] = 0.0f;

    const uint32_t aRel = (uint32_t)((wm * 32 + (lane & 15)) * LDK + (lane >> 4) * 8) * 2;
    const uint32_t bRel = (uint32_t)OBOFF +
        (uint32_t)((wn * 64 + ((lane >> 4) & 1) * 8 + (lane & 7)) * LDK +
                   ((lane >> 3) & 1) * 8) * 2;

    auto load_stage = [&](int c) {
        uint32_t st = smb + (uint32_t)(c & 1) * OSTAGE;
        int k0 = c * 32;
#pragma unroll
        for (int i = 0; i < 2; i++) {
            int e = tid + 256 * i;
            int row = e >> 2, kq = e & 3;
            uint32_t d = st + (uint32_t)(row * LDK + kq * 8) * 2;
            size_t ga = (size_t)(bm + row) * DM + k0 + kq * 8;
            size_t gb = (size_t)(bn + row) * DM + k0 + kq * 8;
            cp16(d, Ah + ga);
            cp16(d + A_PER, Al + ga);
            cp16(d + OBOFF, Bh + gb);
        }
    };

    load_stage(0);
    CP_COMMIT();

    for (int c = 0; c < 32; ++c) {
        CP_WAIT(0);
        __syncthreads();
        uint32_t st = smb + (uint32_t)(c & 1) * OSTAGE;
        uint32_t aBase = st + aRel, bBase = st + bRel;
#pragma unroll
        for (int ks = 0; ks < 2; ++ks) {
            uint32_t koff = ks * 32;
            uint32_t aH[2][4], aL[2][4];
#pragma unroll
            for (int mf = 0; mf < 2; ++mf) {
                ldsm_x4(aH[mf], aBase + koff + mf * (16 * LDK * 2));
                ldsm_x4(aL[mf], aBase + koff + mf * (16 * LDK * 2) + A_PER);
            }
#pragma unroll
            for (int p = 0; p < 4; ++p) {
                uint32_t bH[4];
                ldsm_x4(bH, bBase + koff + p * (16 * LDK * 2));
#pragma unroll
                for (int mf = 0; mf < 2; ++mf) {
                    mma16816h(acc[mf][2 * p], aH[mf], &bH[0]);
                    mma16816h(acc[mf][2 * p + 1], aH[mf], &bH[2]);
                }
#pragma unroll
                for (int mf = 0; mf < 2; ++mf) {
                    mma16816h(acc[mf][2 * p], aL[mf], &bH[0]);
                    mma16816h(acc[mf][2 * p + 1], aL[mf], &bH[2]);
                }
            }
            if (ks == 0 && c + 1 < 32) {
                load_stage(c + 1);
                CP_COMMIT();
            }
        }
    }

    const int g = lane >> 2, t2 = (lane & 3) * 2;
#pragma unroll
    for (int mf = 0; mf < 2; ++mf) {
#pragma unroll
        for (int nf = 0; nf < 8; ++nf) {
            int n = bn + wn * 64 + nf * 8 + t2;
            int m0 = bm + wm * 32 + mf * 16 + g;
            int m1 = m0 + 8;
            *(float2*)(outp + (size_t)m0 * DM + n) =
                make_float2(acc[mf][nf][0], acc[mf][nf][1]);
            *(float2*)(outp + (size_t)m1 * DM + n) =
                make_float2(acc[mf][nf][2], acc[mf][nf][3]);
        }
    }
}

// ---------------------------------------------------------------------------
// Flash attention: round-14 structure (BQ=128, BK=64, 8 warps, 2 CTAs/SM,
// 3-stage KV ring) + Q fragments hoisted into registers (tile-invariant).
// QK fp16x2 (Q single, K hi/lo), PV fp16x1.
// ---------------------------------------------------------------------------
#define FPB 144
#define Q_BYTES (128 * FPB)
#define KV_BYTES (64 * FPB)
#define STG_OFF Q_BYTES
#define STG_SZ (3 * KV_BYTES)
#define NKSTG 3
#define BIAS_OFF (STG_OFF + NKSTG * STG_SZ)   // 101376
#define FSMEM (BIAS_OFF + NKSTG * 192 * 4)    // 103680

__global__ void __launch_bounds__(256, 2) flash_kernel() {
    extern __shared__ char sm[];
    const uint32_t smb = smem_u32(sm);
    const int tid = threadIdx.x, wid = tid >> 5, lane = tid & 31;
    const int g = lane >> 2, tq = lane & 3;
    const int qt = blockIdx.x, h = blockIdx.y, b = blockIdx.z;
    const int bh = b * NH + h;

    const __half* Qg = g_q16 + ((size_t)bh * SS + qt * 128) * DK;
    const __half* Kh = g_kh + (size_t)bh * SS * DK;
    const __half* Kl = g_kl + (size_t)bh * SS * DK;
    const __half* Vg = g_v16 + (size_t)bh * SS * DK;
    float* bw = (float*)(sm + BIAS_OFF);

    // Q tile cp.async (joins group 0)
#pragma unroll
    for (int i = 0; i < 4; i++) {
        int e = tid + 256 * i;
        int row = e >> 3, qd = e & 7;
        cp16(smb + row * FPB + qd * 16, Qg + row * DK + qd * 8);
    }

    auto load_kv = [&](int c) {
        uint32_t st = smb + STG_OFF + (uint32_t)(c % NKSTG) * STG_SZ;
#pragma unroll
        for (int i = 0; i < 2; i++) {
            int e = tid + 256 * i;
            int row = e >> 3, qd = e & 7;
            uint32_t d = st + row * FPB + qd * 16;
            size_t src = (size_t)(c * 64 + row) * DK + qd * 8;
            cp16(d, Kh + src);
            cp16(d + KV_BYTES, Kl + src);
            cp16(d + 2 * KV_BYTES, Vg + src);
        }
    };
    auto load_bias = [&](int c) {
        if (tid < 191) {
            int base = h * (2 * SS - 1) + c * 64 - qt * 128 + 1920;
            bw[(c % NKSTG) * 192 + tid] = g_bias[base + tid];
        }
    };

    load_kv(0);
    CP_COMMIT();
    load_bias(0);
    load_kv(1);
    CP_COMMIT();
    load_bias(1);

    float m_[2] = {-INFINITY, -INFINITY};
    float l_[2] = {0.0f, 0.0f};
    float o[8][4];
#pragma unroll
    for (int j = 0; j < 8; j++)
#pragma unroll
        for (int q = 0; q < 4; q++) o[j][q] = 0.0f;

    const uint32_t aAddr = smb + (uint32_t)(wid * 16 + (lane & 15)) * FPB + (lane >> 4) * 16;
    const uint32_t bRel = (uint32_t)((((lane >> 4) & 1) * 8 + (lane & 7)) * FPB +
                                     ((lane >> 3) & 1) * 16);
    const uint32_t vRel = (uint32_t)((lane & 15) * FPB + (lane >> 4) * 16);
    const int r0 = wid * 16 + g;

    // ---- hoist Q fragments (tile-invariant): 4 ldsm -> 16 regs ----
    CP_WAIT(1);          // group 0 (Q + kv0) complete
    __syncthreads();     // publish cp.async writes across warps
    uint32_t qa[4][4];
#pragma unroll
    for (int kk = 0; kk < 4; ++kk) ldsm_x4(qa[kk], aAddr + kk * 32);

    for (int kt = 0; kt < 32; ++kt) {
        CP_WAIT(1);          // group kt complete (kt+1 may still fly)
        __syncthreads();     // all warps done reading slot (kt-1)%3
        if (kt + 2 < 32) {
            load_kv(kt + 2);
            CP_COMMIT();
            load_bias(kt + 2);
        }
        uint32_t stg = smb + STG_OFF + (uint32_t)(kt % NKSTG) * STG_SZ;
        const float* bwc = bw + (kt % NKSTG) * 192;

        // ---- S = Q Kh^T + Q Kl^T (fp16x2, Q frags from registers) ----
        float s[8][4];
#pragma unroll
        for (int j = 0; j < 8; j++)
#pragma unroll
            for (int q = 0; q < 4; q++) s[j][q] = 0.0f;
#pragma unroll
        for (int kk = 0; kk < 4; ++kk) {
            uint32_t bH[4][4], bL[4][4];
#pragma unroll
            for (int p = 0; p < 4; ++p) {
                uint32_t ba = stg + bRel + p * (16 * FPB) + kk * 32;
                ldsm_x4(bH[p], ba);
                ldsm_x4(bL[p], ba + KV_BYTES);
            }
#pragma unroll
            for (int p = 0; p < 4; ++p) {
                mma16816h(s[2 * p], qa[kk], &bH[p][0]);
                mma16816h(s[2 * p + 1], qa[kk], &bH[p][2]);
            }
#pragma unroll
            for (int p = 0; p < 4; ++p) {
                mma16816h(s[2 * p], qa[kk], &bL[p][0]);
                mma16816h(s[2 * p + 1], qa[kk], &bL[p][2]);
            }
        }

        // ---- bias + online softmax ----
        float mx0 = -INFINITY, mx1 = -INFINITY;
#pragma unroll
        for (int j = 0; j < 8; j++) {
            int c = 8 * j + 2 * tq;
            s[j][0] += bwc[c - r0 + 127];
            s[j][1] += bwc[c + 1 - r0 + 127];
            s[j][2] += bwc[c - (r0 + 8) + 127];
            s[j][3] += bwc[c + 1 - (r0 + 8) + 127];
            mx0 = fmaxf(mx0, fmaxf(s[j][0], s[j][1]));
            mx1 = fmaxf(mx1, fmaxf(s[j][2], s[j][3]));
        }
        mx0 = fmaxf(mx0, __shfl_xor_sync(0xffffffffu, mx0, 1));
        mx0 = fmaxf(mx0, __shfl_xor_sync(0xffffffffu, mx0, 2));
        mx1 = fmaxf(mx1, __shfl_xor_sync(0xffffffffu, mx1, 1));
        mx1 = fmaxf(mx1, __shfl_xor_sync(0xffffffffu, mx1, 2));
        float mn0 = fmaxf(m_[0], mx0), mn1 = fmaxf(m_[1], mx1);
        float al0 = __expf(m_[0] - mn0), al1 = __expf(m_[1] - mn1);

        uint32_t pH[8][2];
        float sum0 = 0.0f, sum1 = 0.0f;
#pragma unroll
        for (int j = 0; j < 8; j++) {
            float e0 = __expf(s[j][0] - mn0), e1 = __expf(s[j][1] - mn0);
            float e2 = __expf(s[j][2] - mn1), e3 = __expf(s[j][3] - mn1);
            sum0 += e0 + e1;
            sum1 += e2 + e3;
            __half2 h01 = __floats2half2_rn(e0, e1);
            __half2 h23 = __floats2half2_rn(e2, e3);
            pH[j][0] = *(uint32_t*)&h01;
            pH[j][1] = *(uint32_t*)&h23;
        }
        sum0 += __shfl_xor_sync(0xffffffffu, sum0, 1);
        sum0 += __shfl_xor_sync(0xffffffffu, sum0, 2);
        sum1 += __shfl_xor_sync(0xffffffffu, sum1, 1);
        sum1 += __shfl_xor_sync(0xffffffffu, sum1, 2);
        l_[0] = l_[0] * al0 + sum0;
        l_[1] = l_[1] * al1 + sum1;
        m_[0] = mn0;
        m_[1] = mn1;
#pragma unroll
        for (int j = 0; j < 8; j++) {
            o[j][0] *= al0; o[j][1] *= al0;
            o[j][2] *= al1; o[j][3] *= al1;
        }

        // ---- O += P V (single fp16 term) ----
        uint32_t vstg = stg + 2 * KV_BYTES;
#pragma unroll
        for (int kk = 0; kk < 4; ++kk) {
            uint32_t aPh[4] = {pH[2 * kk][0], pH[2 * kk][1],
                               pH[2 * kk + 1][0], pH[2 * kk + 1][1]};
            uint32_t vh[4][4];
#pragma unroll
            for (int p = 0; p < 4; ++p)
                ldsm_x4_t(vh[p], vstg + vRel + kk * (16 * FPB) + p * 32);
#pragma unroll
            for (int p = 0; p < 4; ++p) {
                mma16816h(o[2 * p], aPh, &vh[p][0]);
                mma16816h(o[2 * p + 1], aPh, &vh[p][2]);
            }
        }
    }

    // ---- epilogue: ctx = O / l, exact fp16 hi/lo ----
    float inv0 = 1.0f / l_[0], inv1 = 1.0f / l_[1];
    size_t rbase = (size_t)b * SS + qt * 128 + wid * 16 + g;
#pragma unroll
    for (int j = 0; j < 8; j++) {
        int col = h * DK + 8 * j + 2 * tq;
        float x0 = o[j][0] * inv0, x1 = o[j][1] * inv0;
        float x2 = o[j][2] * inv1, x3 = o[j][3] * inv1;
        __half2 h0 = __floats2half2_rn(x0, x1);
        __half2 l0 = __floats2half2_rn(x0 - __low2float(h0), x1 - __high2float(h0));
        __half2 h1 = __floats2half2_rn(x2, x3);
        __half2 l1 = __floats2half2_rn(x2 - __low2float(h1), x3 - __high2float(h1));
        *(__half2*)(g_ch + rbase * DM + col) = h0;
        *(__half2*)(g_cl + rbase * DM + col) = l0;
        *(__half2*)(g_ch + (rbase + 8) * DM + col) = h1;
        *(__half2*)(g_cl + (rbase + 8) * DM + col) = l1;
    }
}

// ---------------------------------------------------------------------------
extern "C" void kernel_launch(void* const* d_in, const int* in_sizes, int n_in,
                              void* d_out, int out_size) {
    const float* hs = (const float*)d_in[0];
    const float* Wq = (const float*)d_in[1];
    const float* Wk = (const float*)d_in[2];
    const float* Wv = (const float*)d_in[3];
    const float* Wo = (const float*)d_in[4];
    const float* rb = (const float*)d_in[5];

    cudaFuncSetAttribute(flash_kernel,
                         cudaFuncAttributeMaxDynamicSharedMemorySize, FSMEM);
    cudaFuncSetAttribute(gemm_qkv_kernel,
                         cudaFuncAttributeMaxDynamicSharedMemorySize, GSMEM);
    cudaFuncSetAttribute(gemm_out_kernel,
                         cudaFuncAttributeMaxDynamicSharedMemorySize, OGSMEM);

    prep_kernel<<<8208, 256>>>((const float4*)hs, Wq, Wk, Wv, Wo, rb);
    gemm_qkv_kernel<<<dim3(MTOT / 128, DM / 128, 3), 256, GSMEM>>>();
    flash_kernel<<<dim3(SS / 128, NH, BB), 256, FSMEM>>>();
    gemm_out_kernel<<<dim3(MTOT / 128, DM / 128), 256, OGSMEM>>>((float*)d_out);
}

// round 17
// speedup vs baseline: 1.1996x; 1.1445x over previous
#include <cuda_runtime.h>
#include <cuda_bf16.h>
#include <cuda_fp16.h>
#include <math.h>
#include <stdint.h>

#define BB 2
#define SS 2048
#define DM 1024
#define NH 16
#define DK 64
#define MTOT (BB * SS)  // 4096

// ---------------- device scratch (allocation-free) ----------------
__device__ float g_bias[NH * (2 * SS - 1)];
__device__ __nv_bfloat16 g_xh[MTOT * DM];     // x bf16 hi/lo (for q,k)
__device__ __nv_bfloat16 g_xl[MTOT * DM];
__device__ __half        g_xh16[MTOT * DM];   // x fp16 hi/lo (for v)
__device__ __half        g_xl16[MTOT * DM];
__device__ __nv_bfloat16 g_wth[2 * DM * DM];  // Wq/Wk ^T hi (K-major)
__device__ __nv_bfloat16 g_wtl[2 * DM * DM];  // lo
__device__ __half        g_wv16[DM * DM];     // Wv^T single fp16
__device__ __half        g_wo16[DM * DM];     // Wo^T single fp16
__device__ __half        g_ch[MTOT * DM];     // ctx fp16 hi (exact split)
__device__ __half        g_cl[MTOT * DM];     // ctx fp16 lo
__device__ __half        g_q16[BB * NH * SS * DK];  // Q single fp16
__device__ __half        g_k16[BB * NH * SS * DK];  // K single fp16
__device__ __half        g_v16[BB * NH * SS * DK];  // V single fp16

// ---------------- PTX helpers (arch-agnostic, sm_80-era) ----------------
__device__ __forceinline__ uint32_t smem_u32(const void* p) {
    uint32_t a;
    asm("{ .reg .u64 t; cvta.to.shared.u64 t, %1; cvt.u32.u64 %0, t; }"
        : "=r"(a) : "l"(p));
    return a;
}
__device__ __forceinline__ void cp16(uint32_t dst, const void* src) {
    uint64_t g = __cvta_generic_to_global(src);
    asm volatile("cp.async.cg.shared.global [%0], [%1], 16;" :: "r"(dst), "l"(g));
}
#define CP_COMMIT() asm volatile("cp.async.commit_group;" ::: "memory")
#define CP_WAIT(n)  asm volatile("cp.async.wait_group %0;" :: "n"(n) : "memory")

__device__ __forceinline__ void ldsm_x4(uint32_t* r, uint32_t addr) {
    asm volatile("ldmatrix.sync.aligned.m8n8.x4.shared.b16 {%0,%1,%2,%3}, [%4];"
                 : "=r"(r[0]), "=r"(r[1]), "=r"(r[2]), "=r"(r[3]) : "r"(addr));
}
__device__ __forceinline__ void ldsm_x4_t(uint32_t* r, uint32_t addr) {
    asm volatile("ldmatrix.sync.aligned.m8n8.x4.trans.shared.b16 {%0,%1,%2,%3}, [%4];"
                 : "=r"(r[0]), "=r"(r[1]), "=r"(r[2]), "=r"(r[3]) : "r"(addr));
}
__device__ __forceinline__ void mma16816(float* c, const uint32_t* a, const uint32_t* b) {
    asm volatile(
        "mma.sync.aligned.m16n8k16.row.col.f32.bf16.bf16.f32 "
        "{%0,%1,%2,%3}, {%4,%5,%6,%7}, {%8,%9}, {%0,%1,%2,%3};"
        : "+f"(c[0]), "+f"(c[1]), "+f"(c[2]), "+f"(c[3])
        : "r"(a[0]), "r"(a[1]), "r"(a[2]), "r"(a[3]), "r"(b[0]), "r"(b[1]));
}
__device__ __forceinline__ void mma16816h(float* c, const uint32_t* a, const uint32_t* b) {
    asm volatile(
        "mma.sync.aligned.m16n8k16.row.col.f32.f16.f16.f32 "
        "{%0,%1,%2,%3}, {%4,%5,%6,%7}, {%8,%9}, {%0,%1,%2,%3};"
        : "+f"(c[0]), "+f"(c[1]), "+f"(c[2]), "+f"(c[3])
        : "r"(a[0]), "r"(a[1]), "r"(a[2]), "r"(a[3]), "r"(b[0]), "r"(b[1]));
}

// ---------------------------------------------------------------------------
// Fused prep: blocks [0,4096) split x; [4096,8192) transpose+split W;
// [8192,8208) bias table.
// ---------------------------------------------------------------------------
__global__ void __launch_bounds__(256) prep_kernel(
    const float4* __restrict__ src,
    const float* __restrict__ W0, const float* __restrict__ W1,
    const float* __restrict__ W2, const float* __restrict__ W3,
    const float* __restrict__ rel_bias)
{
    int bid = blockIdx.x;
    int tid = threadIdx.x;
    if (bid < 4096) {
        int i = bid * 256 + tid;
        float4 x = src[i];
        __nv_bfloat162 hA = __floats2bfloat162_rn(x.x, x.y);
        __nv_bfloat162 hB = __floats2bfloat162_rn(x.z, x.w);
        __nv_bfloat162 lA = __floats2bfloat162_rn(x.x - __bfloat162float(hA.x),
                                                  x.y - __bfloat162float(hA.y));
        __nv_bfloat162 lB = __floats2bfloat162_rn(x.z - __bfloat162float(hB.x),
                                                  x.w - __bfloat162float(hB.y));
        *(__nv_bfloat162*)(g_xh + 4 * i) = hA;
        *(__nv_bfloat162*)(g_xh + 4 * i + 2) = hB;
        *(__nv_bfloat162*)(g_xl + 4 * i) = lA;
        *(__nv_bfloat162*)(g_xl + 4 * i + 2) = lB;
        __half2 h16A = __floats2half2_rn(x.x, x.y);
        __half2 h16B = __floats2half2_rn(x.z, x.w);
        __half2 l16A = __floats2half2_rn(x.x - __low2float(h16A),
                                         x.y - __high2float(h16A));
        __half2 l16B = __floats2half2_rn(x.z - __low2float(h16B),
                                         x.w - __high2float(h16B));
        *(__half2*)(g_xh16 + 4 * i) = h16A;
        *(__half2*)(g_xh16 + 4 * i + 2) = h16B;
        *(__half2*)(g_xl16 + 4 * i) = l16A;
        *(__half2*)(g_xl16 + 4 * i + 2) = l16B;
    } else if (bid < 8192) {
        __shared__ float t[32][33];
        int e = bid - 4096;
        int z = e >> 10;
        int rem = e & 1023;
        int bx = rem >> 5, by = rem & 31;
        const float* W = z == 0 ? W0 : z == 1 ? W1 : z == 2 ? W2 : W3;
        int k0 = bx * 32, n0 = by * 32;
        int tx = tid & 31, ty = tid >> 5;
#pragma unroll
        for (int r = 0; r < 32; r += 8)
            t[ty + r][tx] = W[(size_t)(k0 + ty + r) * DM + n0 + tx];
        __syncthreads();
#pragma unroll
        for (int r = 0; r < 32; r += 8) {
            float x = t[tx][ty + r];
            size_t o = (size_t)(n0 + ty + r) * DM + k0 + tx;
            if (z < 2) {
                __nv_bfloat16 h = __float2bfloat16_rn(x);
                g_wth[(size_t)z * DM * DM + o] = h;
                g_wtl[(size_t)z * DM * DM + o] =
                    __float2bfloat16_rn(x - __bfloat162float(h));
            } else if (z == 2) {
                g_wv16[o] = __float2half_rn(x);
            } else {
                g_wo16[o] = __float2half_rn(x);
            }
        }
    } else {
        int h = bid - 8192;
        for (int idx = tid; idx < 2 * SS - 1; idx += 256) {
            int rel = idx - (SS - 1);
            int base = (rel > 0) ? 16 : 0;
            int rp = rel < 0 ? -rel : rel;
            int bucket;
            if (rp < 8) {
                bucket = rp;
            } else {
                float v = logf((float)rp * 0.125f) / logf(16.0f) * 8.0f;
                int bb = 8 + (int)v;
                bucket = bb < 15 ? bb : 15;
            }
            g_bias[h * (2 * SS - 1) + idx] = rel_bias[(base + bucket) * NH + h];
        }
    }
}

// ---------------------------------------------------------------------------
// Fused QKV GEMM: z=0,1 -> bf16x3 (q,k); z=2 -> fp16x2 (v).
// Epilogue: q, k, v all single fp16.
// ---------------------------------------------------------------------------
#define LDK 40
#define A_PER (128 * LDK * 2)
#define B_PER (128 * LDK * 2)
#define BOFF (2 * A_PER)
#define STAGE (2 * A_PER + 2 * B_PER)
#define GSMEM (2 * STAGE)

__global__ void __launch_bounds__(256, 2) gemm_qkv_kernel() {
    const int mode = blockIdx.z;
    const bool isv = (mode == 2);
    const __nv_bfloat16* Ah = isv ? (const __nv_bfloat16*)g_xh16 : g_xh;
    const __nv_bfloat16* Al = isv ? (const __nv_bfloat16*)g_xl16 : g_xl;
    const __nv_bfloat16* Bh = isv ? (const __nv_bfloat16*)g_wv16
                                  : g_wth + (size_t)mode * DM * DM;
    const __nv_bfloat16* Bl = isv ? nullptr : g_wtl + (size_t)mode * DM * DM;

    extern __shared__ char sm[];
    const uint32_t smb = smem_u32(sm);
    const int tid = threadIdx.x;
    const int wid = tid >> 5, lane = tid & 31;
    const int wm = wid >> 1, wn = wid & 1;
    const int bm = blockIdx.x * 128, bn = blockIdx.y * 128;

    float acc[2][8][4];
#pragma unroll
    for (int i = 0; i < 2; i++)
#pragma unroll
        for (int j = 0; j < 8; j++)
#pragma unroll
            for (int q = 0; q < 4; q++) acc[i][j][q] = 0.0f;

    const uint32_t aRel = (uint32_t)((wm * 32 + (lane & 15)) * LDK + (lane >> 4) * 8) * 2;
    const uint32_t bRel = (uint32_t)BOFF +
        (uint32_t)((wn * 64 + ((lane >> 4) & 1) * 8 + (lane & 7)) * LDK +
                   ((lane >> 3) & 1) * 8) * 2;

    auto load_stage = [&](int c) {
        uint32_t st = smb + (uint32_t)(c & 1) * STAGE;
        int k0 = c * 32;
#pragma unroll
        for (int i = 0; i < 2; i++) {
            int e = tid + 256 * i;
            int row = e >> 2, kq = e & 3;
            uint32_t d = st + (uint32_t)(row * LDK + kq * 8) * 2;
            size_t ga = (size_t)(bm + row) * DM + k0 + kq * 8;
            size_t gb = (size_t)(bn + row) * DM + k0 + kq * 8;
            cp16(d, Ah + ga);
            cp16(d + A_PER, Al + ga);
            cp16(d + BOFF, Bh + gb);
            if (!isv) cp16(d + BOFF + B_PER, Bl + gb);
        }
    };

    load_stage(0);
    CP_COMMIT();

    for (int c = 0; c < 32; ++c) {
        CP_WAIT(0);
        __syncthreads();
        uint32_t st = smb + (uint32_t)(c & 1) * STAGE;
        uint32_t aBase = st + aRel, bBase = st + bRel;
#pragma unroll
        for (int ks = 0; ks < 2; ++ks) {
            uint32_t koff = ks * 32;
            uint32_t aH[2][4], aL[2][4];
#pragma unroll
            for (int mf = 0; mf < 2; ++mf) {
                ldsm_x4(aH[mf], aBase + koff + mf * (16 * LDK * 2));
                ldsm_x4(aL[mf], aBase + koff + mf * (16 * LDK * 2) + A_PER);
            }
            if (!isv) {
#pragma unroll
                for (int p = 0; p < 4; ++p) {
                    uint32_t bH[4], bL[4];
                    uint32_t ba = bBase + koff + p * (16 * LDK * 2);
                    ldsm_x4(bH, ba);
                    ldsm_x4(bL, ba + B_PER);
#pragma unroll
                    for (int mf = 0; mf < 2; ++mf) {
                        mma16816(acc[mf][2 * p], aH[mf], &bH[0]);
                        mma16816(acc[mf][2 * p + 1], aH[mf], &bH[2]);
                    }
#pragma unroll
                    for (int mf = 0; mf < 2; ++mf) {
                        mma16816(acc[mf][2 * p], aH[mf], &bL[0]);
                        mma16816(acc[mf][2 * p + 1], aH[mf], &bL[2]);
                    }
#pragma unroll
                    for (int mf = 0; mf < 2; ++mf) {
                        mma16816(acc[mf][2 * p], aL[mf], &bH[0]);
                        mma16816(acc[mf][2 * p + 1], aL[mf], &bH[2]);
                    }
                }
            } else {
#pragma unroll
                for (int p = 0; p < 4; ++p) {
                    uint32_t bH[4];
                    ldsm_x4(bH, bBase + koff + p * (16 * LDK * 2));
#pragma unroll
                    for (int mf = 0; mf < 2; ++mf) {
                        mma16816h(acc[mf][2 * p], aH[mf], &bH[0]);
                        mma16816h(acc[mf][2 * p + 1], aH[mf], &bH[2]);
                    }
#pragma unroll
                    for (int mf = 0; mf < 2; ++mf) {
                        mma16816h(acc[mf][2 * p], aL[mf], &bH[0]);
                        mma16816h(acc[mf][2 * p + 1], aL[mf], &bH[2]);
                    }
                }
            }
            if (ks == 0 && c + 1 < 32) {
                load_stage(c + 1);
                CP_COMMIT();
            }
        }
    }

    const int g = lane >> 2, t2 = (lane & 3) * 2;
#pragma unroll
    for (int mf = 0; mf < 2; ++mf) {
#pragma unroll
        for (int nf = 0; nf < 8; ++nf) {
            int n = bn + wn * 64 + nf * 8 + t2;
            int m0 = bm + wm * 32 + mf * 16 + g;
            int m1 = m0 + 8;
            int hh = n >> 6, d = n & 63;
            size_t o0 = (((size_t)(m0 >> 11) * NH + hh) * SS + (m0 & (SS - 1))) * DK + d;
            size_t o1 = (((size_t)(m1 >> 11) * NH + hh) * SS + (m1 & (SS - 1))) * DK + d;
            float v0 = acc[mf][nf][0], v1 = acc[mf][nf][1];
            float v2 = acc[mf][nf][2], v3 = acc[mf][nf][3];
            __half* Out = mode == 0 ? g_q16 : (mode == 1 ? g_k16 : g_v16);
            *(__half2*)(Out + o0) = __floats2half2_rn(v0, v1);
            *(__half2*)(Out + o1) = __floats2half2_rn(v2, v3);
        }
    }
}

// ---------------------------------------------------------------------------
// Output GEMM (unchanged).
// ---------------------------------------------------------------------------
#define OBOFF (2 * A_PER)
#define OSTAGE (3 * A_PER)
#define OGSMEM (2 * OSTAGE)

__global__ void __launch_bounds__(256, 2) gemm_out_kernel(float* __restrict__ outp) {
    const __half* Ah = g_ch;
    const __half* Al = g_cl;
    const __half* Bh = g_wo16;

    extern __shared__ char sm[];
    const uint32_t smb = smem_u32(sm);
    const int tid = threadIdx.x;
    const int wid = tid >> 5, lane = tid & 31;
    const int wm = wid >> 1, wn = wid & 1;
    const int bm = blockIdx.x * 128, bn = blockIdx.y * 128;

    float acc[2][8][4];
#pragma unroll
    for (int i = 0; i < 2; i++)
#pragma unroll
        for (int j = 0; j < 8; j++)
#pragma unroll
            for (int q = 0; q < 4; q++) acc[i][j][q] = 0.0f;

    const uint32_t aRel = (uint32_t)((wm * 32 + (lane & 15)) * LDK + (lane >> 4) * 8) * 2;
    const uint32_t bRel = (uint32_t)OBOFF +
        (uint32_t)((wn * 64 + ((lane >> 4) & 1) * 8 + (lane & 7)) * LDK +
                   ((lane >> 3) & 1) * 8) * 2;

    auto load_stage = [&](int c) {
        uint32_t st = smb + (uint32_t)(c & 1) * OSTAGE;
        int k0 = c * 32;
#pragma unroll
        for (int i = 0; i < 2; i++) {
            int e = tid + 256 * i;
            int row = e >> 2, kq = e & 3;
            uint32_t d = st + (uint32_t)(row * LDK + kq * 8) * 2;
            size_t ga = (size_t)(bm + row) * DM + k0 + kq * 8;
            size_t gb = (size_t)(bn + row) * DM + k0 + kq * 8;
            cp16(d, Ah + ga);
            cp16(d + A_PER, Al + ga);
            cp16(d + OBOFF, Bh + gb);
        }
    };

    load_stage(0);
    CP_COMMIT();

    for (int c = 0; c < 32; ++c) {
        CP_WAIT(0);
        __syncthreads();
        uint32_t st = smb + (uint32_t)(c & 1) * OSTAGE;
        uint32_t aBase = st + aRel, bBase = st + bRel;
#pragma unroll
        for (int ks = 0; ks < 2; ++ks) {
            uint32_t koff = ks * 32;
            uint32_t aH[2][4], aL[2][4];
#pragma unroll
            for (int mf = 0; mf < 2; ++mf) {
                ldsm_x4(aH[mf], aBase + koff + mf * (16 * LDK * 2));
                ldsm_x4(aL[mf], aBase + koff + mf * (16 * LDK * 2) + A_PER);
            }
#pragma unroll
            for (int p = 0; p < 4; ++p) {
                uint32_t bH[4];
                ldsm_x4(bH, bBase + koff + p * (16 * LDK * 2));
#pragma unroll
                for (int mf = 0; mf < 2; ++mf) {
                    mma16816h(acc[mf][2 * p], aH[mf], &bH[0]);
                    mma16816h(acc[mf][2 * p + 1], aH[mf], &bH[2]);
                }
#pragma unroll
                for (int mf = 0; mf < 2; ++mf) {
                    mma16816h(acc[mf][2 * p], aL[mf], &bH[0]);
                    mma16816h(acc[mf][2 * p + 1], aL[mf], &bH[2]);
                }
            }
            if (ks == 0 && c + 1 < 32) {
                load_stage(c + 1);
                CP_COMMIT();
            }
        }
    }

    const int g = lane >> 2, t2 = (lane & 3) * 2;
#pragma unroll
    for (int mf = 0; mf < 2; ++mf) {
#pragma unroll
        for (int nf = 0; nf < 8; ++nf) {
            int n = bn + wn * 64 + nf * 8 + t2;
            int m0 = bm + wm * 32 + mf * 16 + g;
            int m1 = m0 + 8;
            *(float2*)(outp + (size_t)m0 * DM + n) =
                make_float2(acc[mf][nf][0], acc[mf][nf][1]);
            *(float2*)(outp + (size_t)m1 * DM + n) =
                make_float2(acc[mf][nf][2], acc[mf][nf][3]);
        }
    }
}

// ---------------------------------------------------------------------------
// Flash attention: BQ=128, BK=64, 8 warps, 2 CTAs/SM, 3-stage KV ring,
// Q fragments hoisted. QK fp16 SINGLE term, PV fp16 single term.
// l-sum reduction deferred to epilogue (per-thread partials in the loop).
// ---------------------------------------------------------------------------
#define FPB 144
#define Q_BYTES (128 * FPB)
#define KV_BYTES (64 * FPB)
#define STG_OFF Q_BYTES
#define STG_SZ (2 * KV_BYTES)            // k16, v16
#define NKSTG 3
#define BIAS_OFF (STG_OFF + NKSTG * STG_SZ)   // 73728
#define FSMEM (BIAS_OFF + NKSTG * 192 * 4)    // 76032

__global__ void __launch_bounds__(256, 2) flash_kernel() {
    extern __shared__ char sm[];
    const uint32_t smb = smem_u32(sm);
    const int tid = threadIdx.x, wid = tid >> 5, lane = tid & 31;
    const int g = lane >> 2, tq = lane & 3;
    const int qt = blockIdx.x, h = blockIdx.y, b = blockIdx.z;
    const int bh = b * NH + h;

    const __half* Qg = g_q16 + ((size_t)bh * SS + qt * 128) * DK;
    const __half* Kg = g_k16 + (size_t)bh * SS * DK;
    const __half* Vg = g_v16 + (size_t)bh * SS * DK;
    float* bw = (float*)(sm + BIAS_OFF);

    // Q tile cp.async (joins group 0)
#pragma unroll
    for (int i = 0; i < 4; i++) {
        int e = tid + 256 * i;
        int row = e >> 3, qd = e & 7;
        cp16(smb + row * FPB + qd * 16, Qg + row * DK + qd * 8);
    }

    auto load_kv = [&](int c) {
        uint32_t st = smb + STG_OFF + (uint32_t)(c % NKSTG) * STG_SZ;
#pragma unroll
        for (int i = 0; i < 2; i++) {
            int e = tid + 256 * i;
            int row = e >> 3, qd = e & 7;
            uint32_t d = st + row * FPB + qd * 16;
            size_t src = (size_t)(c * 64 + row) * DK + qd * 8;
            cp16(d, Kg + src);
            cp16(d + KV_BYTES, Vg + src);
        }
    };
    auto load_bias = [&](int c) {
        if (tid < 191) {
            int base = h * (2 * SS - 1) + c * 64 - qt * 128 + 1920;
            bw[(c % NKSTG) * 192 + tid] = g_bias[base + tid];
        }
    };

    load_kv(0);
    CP_COMMIT();
    load_bias(0);
    load_kv(1);
    CP_COMMIT();
    load_bias(1);

    float m_[2] = {-INFINITY, -INFINITY};
    float l_[2] = {0.0f, 0.0f};   // per-thread partial row sums (deferred reduce)
    float o[8][4];
#pragma unroll
    for (int j = 0; j < 8; j++)
#pragma unroll
        for (int q = 0; q < 4; q++) o[j][q] = 0.0f;

    const uint32_t aAddr = smb + (uint32_t)(wid * 16 + (lane & 15)) * FPB + (lane >> 4) * 16;
    const uint32_t bRel = (uint32_t)((((lane >> 4) & 1) * 8 + (lane & 7)) * FPB +
                                     ((lane >> 3) & 1) * 16);
    const uint32_t vRel = (uint32_t)((lane & 15) * FPB + (lane >> 4) * 16);
    const int r0 = wid * 16 + g;

    // ---- hoist Q fragments (tile-invariant) ----
    CP_WAIT(1);
    __syncthreads();
    uint32_t qa[4][4];
#pragma unroll
    for (int kk = 0; kk < 4; ++kk) ldsm_x4(qa[kk], aAddr + kk * 32);

    for (int kt = 0; kt < 32; ++kt) {
        CP_WAIT(1);
        __syncthreads();
        if (kt + 2 < 32) {
            load_kv(kt + 2);
            CP_COMMIT();
            load_bias(kt + 2);
        }
        uint32_t stg = smb + STG_OFF + (uint32_t)(kt % NKSTG) * STG_SZ;
        const float* bwc = bw + (kt % NKSTG) * 192;

        // ---- S = Q K^T (single fp16 term) ----
        float s[8][4];
#pragma unroll
        for (int j = 0; j < 8; j++)
#pragma unroll
            for (int q = 0; q < 4; q++) s[j][q] = 0.0f;
#pragma unroll
        for (int kk = 0; kk < 4; ++kk) {
            uint32_t bH[4][4];
#pragma unroll
            for (int p = 0; p < 4; ++p)
                ldsm_x4(bH[p], stg + bRel + p * (16 * FPB) + kk * 32);
#pragma unroll
            for (int p = 0; p < 4; ++p) {
                mma16816h(s[2 * p], qa[kk], &bH[p][0]);
                mma16816h(s[2 * p + 1], qa[kk], &bH[p][2]);
            }
        }

        // ---- bias + online softmax ----
        float mx0 = -INFINITY, mx1 = -INFINITY;
#pragma unroll
        for (int j = 0; j < 8; j++) {
            int c = 8 * j + 2 * tq;
            s[j][0] += bwc[c - r0 + 127];
            s[j][1] += bwc[c + 1 - r0 + 127];
            s[j][2] += bwc[c - (r0 + 8) + 127];
            s[j][3] += bwc[c + 1 - (r0 + 8) + 127];
            mx0 = fmaxf(mx0, fmaxf(s[j][0], s[j][1]));
            mx1 = fmaxf(mx1, fmaxf(s[j][2], s[j][3]));
        }
        mx0 = fmaxf(mx0, __shfl_xor_sync(0xffffffffu, mx0, 1));
        mx0 = fmaxf(mx0, __shfl_xor_sync(0xffffffffu, mx0, 2));
        mx1 = fmaxf(mx1, __shfl_xor_sync(0xffffffffu, mx1, 1));
        mx1 = fmaxf(mx1, __shfl_xor_sync(0xffffffffu, mx1, 2));
        float mn0 = fmaxf(m_[0], mx0), mn1 = fmaxf(m_[1], mx1);
        float al0 = __expf(m_[0] - mn0), al1 = __expf(m_[1] - mn1);

        uint32_t pH[8][2];
        float sum0 = 0.0f, sum1 = 0.0f;   // per-thread local column sums
#pragma unroll
        for (int j = 0; j < 8; j++) {
            float e0 = __expf(s[j][0] - mn0), e1 = __expf(s[j][1] - mn0);
            float e2 = __expf(s[j][2] - mn1), e3 = __expf(s[j][3] - mn1);
            sum0 += e0 + e1;
            sum1 += e2 + e3;
            __half2 h01 = __floats2half2_rn(e0, e1);
            __half2 h23 = __floats2half2_rn(e2, e3);
            pH[j][0] = *(uint32_t*)&h01;
            pH[j][1] = *(uint32_t*)&h23;
        }
        // deferred: NO shfl here; al factors are quad-uniform so partials compose
        l_[0] = l_[0] * al0 + sum0;
        l_[1] = l_[1] * al1 + sum1;
        m_[0] = mn0;
        m_[1] = mn1;
#pragma unroll
        for (int j = 0; j < 8; j++) {
            o[j][0] *= al0; o[j][1] *= al0;
            o[j][2] *= al1; o[j][3] *= al1;
        }

        // ---- O += P V (single fp16 term) ----
        uint32_t vstg = stg + KV_BYTES;
#pragma unroll
        for (int kk = 0; kk < 4; ++kk) {
            uint32_t aPh[4] = {pH[2 * kk][0], pH[2 * kk][1],
                               pH[2 * kk + 1][0], pH[2 * kk + 1][1]};
            uint32_t vh[4][4];
#pragma unroll
            for (int p = 0; p < 4; ++p)
                ldsm_x4_t(vh[p], vstg + vRel + kk * (16 * FPB) + p * 32);
#pragma unroll
            for (int p = 0; p < 4; ++p) {
                mma16816h(o[2 * p], aPh, &vh[p][0]);
                mma16816h(o[2 * p + 1], aPh, &vh[p][2]);
            }
        }
    }

    // ---- epilogue: reduce l across quad, then ctx = O / l (fp16 hi/lo) ----
    float l0 = l_[0], l1 = l_[1];
    l0 += __shfl_xor_sync(0xffffffffu, l0, 1);
    l0 += __shfl_xor_sync(0xffffffffu, l0, 2);
    l1 += __shfl_xor_sync(0xffffffffu, l1, 1);
    l1 += __shfl_xor_sync(0xffffffffu, l1, 2);
    float inv0 = 1.0f / l0, inv1 = 1.0f / l1;
    size_t rbase = (size_t)b * SS + qt * 128 + wid * 16 + g;
#pragma unroll
    for (int j = 0; j < 8; j++) {
        int col = h * DK + 8 * j + 2 * tq;
        float x0 = o[j][0] * inv0, x1 = o[j][1] * inv0;
        float x2 = o[j][2] * inv1, x3 = o[j][3] * inv1;
        __half2 h0 = __floats2half2_rn(x0, x1);
        __half2 l0h = __floats2half2_rn(x0 - __low2float(h0), x1 - __high2float(h0));
        __half2 h1 = __floats2half2_rn(x2, x3);
        __half2 l1h = __floats2half2_rn(x2 - __low2float(h1), x3 - __high2float(h1));
        *(__half2*)(g_ch + rbase * DM + col) = h0;
        *(__half2*)(g_cl + rbase * DM + col) = l0h;
        *(__half2*)(g_ch + (rbase + 8) * DM + col) = h1;
        *(__half2*)(g_cl + (rbase + 8) * DM + col) = l1h;
    }
}

// ---------------------------------------------------------------------------
extern "C" void kernel_launch(void* const* d_in, const int* in_sizes, int n_in,
                              void* d_out, int out_size) {
    const float* hs = (const float*)d_in[0];
    const float* Wq = (const float*)d_in[1];
    const float* Wk = (const float*)d_in[2];
    const float* Wv = (const float*)d_in[3];
    const float* Wo = (const float*)d_in[4];
    const float* rb = (const float*)d_in[5];

    cudaFuncSetAttribute(flash_kernel,
                         cudaFuncAttributeMaxDynamicSharedMemorySize, FSMEM);
    cudaFuncSetAttribute(gemm_qkv_kernel,
                         cudaFuncAttributeMaxDynamicSharedMemorySize, GSMEM);
    cudaFuncSetAttribute(gemm_out_kernel,
                         cudaFuncAttributeMaxDynamicSharedMemorySize, OGSMEM);

    prep_kernel<<<8208, 256>>>((const float4*)hs, Wq, Wk, Wv, Wo, rb);
    gemm_qkv_kernel<<<dim3(MTOT / 128, DM / 128, 3), 256, GSMEM>>>();
    flash_kernel<<<dim3(SS / 128, NH, BB), 256, FSMEM>>>();
    gemm_out_kernel<<<dim3(MTOT / 128, DM / 128), 256, OGSMEM>>>((float*)d_out);
}